// round 6
// baseline (speedup 1.0000x reference)
#include <cuda_runtime.h>

#define K1v 16
#define BATCH 16
#define CH 32
#define NP 4096
#define EDG (NP*K1v)          // 65536
#define TP 16                 // points per CTA
#define RR_S 260              // padded activation row stride (floats)
#define INVC 0.9999950000374997f  // 1/sqrt(1+1e-5)

// Scratch (no cudaMalloc allowed)
__device__ int   g_idx[BATCH*NP*K1v];     // 4 MB
__device__ float g_featT[BATCH*NP*CH];    // 8 MB (B,P,C)
__device__ int   g_brk[BATCH*256];        // per-chunk first-break

typedef unsigned long long u64;

__device__ __forceinline__ u64 fma2(u64 a, u64 b, u64 c) {
    u64 d;
    asm("fma.rn.f32x2 %0, %1, %2, %3;" : "=l"(d) : "l"(a), "l"(b), "l"(c));
    return d;
}
__device__ __forceinline__ u64 pack2(float x, float y) {
    u64 d;
    asm("mov.b64 %0, {%1, %2};" : "=l"(d) : "f"(x), "f"(y));
    return d;
}
__device__ __forceinline__ void unpack2(u64 v, float& x, float& y) {
    asm("mov.b64 {%0, %1}, %2;" : "=f"(x), "=f"(y) : "l"(v));
}

// ---------------------------------------------------------------------------
// Edge preprocessing: prep (defaults + per-chunk break) -> scatter
// ---------------------------------------------------------------------------
__global__ void prep_kernel(const int* __restrict__ ef) {
    const int blk   = blockIdx.x;          // 0..BATCH*256-1
    const int b     = blk >> 8;
    const int chunk = blk & 255;
    const int t     = threadIdx.x;         // 256
    const int e     = chunk * 256 + t;

    g_idx[(b << 16) | e] = NP - K1v + (e & 15);   // default idx0

    const int* __restrict__ pf = ef + (size_t)b * 2 * EDG;
    int brk = EDG;
    if (e > 0 && pf[e] == 0 && pf[e - 1] != 0) brk = e;

    __shared__ int s[256];
    s[t] = brk;
    __syncthreads();
    #pragma unroll
    for (int off = 128; off > 0; off >>= 1) {
        if (t < off) s[t] = min(s[t], s[t + off]);
        __syncthreads();
    }
    if (t == 0) g_brk[b * 256 + chunk] = s[0];
}

__global__ void scatter_kernel(const int* __restrict__ ef) {
    const int b  = blockIdx.y;
    const int e0 = blockIdx.x * 256;
    const int t  = threadIdx.x;
    const int e  = e0 + t;
    const int* __restrict__ pf = ef + (size_t)b * 2 * EDG;
    const int* __restrict__ tg = pf + EDG;

    __shared__ int s[272];
    __shared__ int sm2[256];
    sm2[t] = g_brk[b * 256 + t];
    for (int i = t; i < 272; i += 256) {
        int src = e0 - 16 + i;
        s[i] = (src >= 0) ? pf[src] : -1;
    }
    __syncthreads();
    #pragma unroll
    for (int off = 128; off > 0; off >>= 1) {
        if (t < off) sm2[t] = min(sm2[t], sm2[t + off]);
        __syncthreads();
    }
    const int broken = sm2[0];

    int v = s[t + 16];
    int j = 0, m = e, si = t + 16;
    while (m > 0 && j < 16 && s[si - 1] == v) { m--; si--; j++; }
    if (j < 16 && e < broken && (unsigned)v < (unsigned)NP)
        g_idx[(((size_t)b * NP + v) << 4) + j] = tg[e];
}

// ---------------------------------------------------------------------------
// Transpose features (B,C,P) -> (B,P,C)
// ---------------------------------------------------------------------------
__global__ void transpose_kernel(const float* __restrict__ f) {
    __shared__ float tile[32][33];
    int b  = blockIdx.y;
    int p0 = blockIdx.x * 32;
    int tx = threadIdx.x, ty = threadIdx.y;  // (32, 8)
    #pragma unroll
    for (int i = 0; i < 32; i += 8)
        tile[ty + i][tx] = f[((size_t)b * CH + ty + i) * NP + p0 + tx];
    __syncthreads();
    #pragma unroll
    for (int i = 0; i < 32; i += 8)
        g_featT[((size_t)b * NP + p0 + ty + i) * CH + tx] = tile[tx][ty + i];
}

// ---------------------------------------------------------------------------
// GEMM stage. Thread tile 4o x 16r. lane = oq*4 + ri (oq 0..7, ri 0..3).
// Thread rows: r = w*64 + g*16 + ri*4 + {0..3}, g = 0..3; pt(g) = w*4 + g.
// x operands loaded directly as ulonglong2 (adjacent rows = packed pair).
// MODE 0: dst[o][r] = relu(acc*s + pb0[o][pt])
// MODE 1: dst[o][r] = relu(acc*s + b[o])
// MODE 2: red[o][pt] += rows of relu(acc*s + b[o])  (shfl over ri)
// ---------------------------------------------------------------------------
template<int MODE>
__device__ __forceinline__ void gemm_stage(
    const float* __restrict__ src,   // [32][RR_S]
    float*       __restrict__ dst,
    const float* __restrict__ Wt,    // [32][OSTR]
    int OSTR, int o0,
    const float* __restrict__ scal, const float* __restrict__ bias,
    const float* __restrict__ pb0s,
    int w, int ri)
{
    u64 acc[4][8];
    #pragma unroll
    for (int o = 0; o < 4; o++)
        #pragma unroll
        for (int j = 0; j < 8; j++) acc[o][j] = 0ull;

    const float* xb = src + w * 64 + ri * 4;
    const float* wb = Wt + o0;

    #pragma unroll 8
    for (int k = 0; k < 32; k++) {
        float4 wv = *(const float4*)(wb + k * OSTR);
        u64 wd0 = pack2(wv.x, wv.x), wd1 = pack2(wv.y, wv.y);
        u64 wd2 = pack2(wv.z, wv.z), wd3 = pack2(wv.w, wv.w);
        u64 xp[8];
        #pragma unroll
        for (int g = 0; g < 4; g++) {
            ulonglong2 xx = *(const ulonglong2*)(xb + k * RR_S + g * 16);
            xp[2*g]   = xx.x;
            xp[2*g+1] = xx.y;
        }
        #pragma unroll
        for (int j = 0; j < 8; j++) {
            acc[0][j] = fma2(wd0, xp[j], acc[0][j]);
            acc[1][j] = fma2(wd1, xp[j], acc[1][j]);
            acc[2][j] = fma2(wd2, xp[j], acc[2][j]);
            acc[3][j] = fma2(wd3, xp[j], acc[3][j]);
        }
    }

    #pragma unroll
    for (int o = 0; o < 4; o++) {
        int og = o0 + o;
        float s = scal[og];
        if (MODE == 2) {
            float bv = bias[og];
            #pragma unroll
            for (int g = 0; g < 4; g++) {
                float h0, h1, h2, h3;
                unpack2(acc[o][2*g],   h0, h1);
                unpack2(acc[o][2*g+1], h2, h3);
                float pa = fmaxf(fmaf(h0, s, bv), 0.f) + fmaxf(fmaf(h1, s, bv), 0.f)
                         + fmaxf(fmaf(h2, s, bv), 0.f) + fmaxf(fmaf(h3, s, bv), 0.f);
                pa += __shfl_xor_sync(0xffffffffu, pa, 1);
                pa += __shfl_xor_sync(0xffffffffu, pa, 2);
                if (ri == 0)
                    dst[og * TP + w * 4 + g] = pa;
            }
        } else {
            #pragma unroll
            for (int g = 0; g < 4; g++) {
                float bv = (MODE == 0) ? pb0s[og * TP + w * 4 + g] : bias[og];
                float h0, h1, h2, h3;
                unpack2(acc[o][2*g],   h0, h1);
                unpack2(acc[o][2*g+1], h2, h3);
                h0 = fmaxf(fmaf(h0, s, bv), 0.f);
                h1 = fmaxf(fmaf(h1, s, bv), 0.f);
                h2 = fmaxf(fmaf(h2, s, bv), 0.f);
                h3 = fmaxf(fmaf(h3, s, bv), 0.f);
                *(float4*)(dst + og * RR_S + w * 64 + g * 16 + ri * 4)
                    = make_float4(h0, h1, h2, h3);
            }
        }
    }
}

// ---------------------------------------------------------------------------
// Main kernel, 128 threads, TP=16 points (256 rows). 2 CTAs/SM.
// Dynamic smem (float offsets):
//   0     sWt0l[32c][32o]  1024 sWt0h  2048 sWt1  3072 sWt2[32c][64o]
//   5120  sWtc[32c][64o]   7168 ss0,sb0,ss1,sb1(32ea)  7296 ss2,sb2,ssc,sbc(64ea)
//   7552  CF[32c][16]      8064 pb0s[32o][16]   8576 red[64o][16]
//   9600  XA[32][260]      17920 XB[32][260]    -> 26240 floats (102.5 KB)
// ---------------------------------------------------------------------------
#define SMEM_FLOATS 26240

__global__ void __launch_bounds__(128, 2) main_kernel(
    const float* __restrict__ W0, const float* __restrict__ g0, const float* __restrict__ bb0,
    const float* __restrict__ W1, const float* __restrict__ g1, const float* __restrict__ bb1,
    const float* __restrict__ W2, const float* __restrict__ g2, const float* __restrict__ bb2,
    const float* __restrict__ SW, const float* __restrict__ sg, const float* __restrict__ sb,
    float* __restrict__ out)
{
    extern __shared__ float sm[];
    float* sWt0l = sm;
    float* sWt0h = sm + 1024;
    float* sWt1  = sm + 2048;
    float* sWt2  = sm + 3072;
    float* sWtc  = sm + 5120;
    float* ss0   = sm + 7168;
    float* sb0   = sm + 7200;
    float* ss1   = sm + 7232;
    float* sb1   = sm + 7264;
    float* ss2   = sm + 7296;
    float* sb2   = sm + 7360;
    float* ssc   = sm + 7424;
    float* sbc   = sm + 7488;
    float* CF    = sm + 7552;
    float* pb0s  = sm + 8064;
    float* red   = sm + 8576;
    float* XA    = sm + 9600;
    float* XB    = sm + 17920;

    const int tid  = threadIdx.x;
    const int base = blockIdx.x * TP;
    const int b    = base >> 12;
    const int p0   = base & (NP - 1);

    // ---- stage weights (transposed [c][o]) and scales ----
    for (int i = tid; i < 2048; i += 128) {        // W0: (32o, 64c)
        int o = i >> 6, c = i & 63;
        float w = W0[i];
        if (c < 32) sWt0l[c * 32 + o] = w;
        else        sWt0h[(c - 32) * 32 + o] = w;
    }
    for (int i = tid; i < 1024; i += 128) {        // W1
        int o = i >> 5, c = i & 31;
        sWt1[c * 32 + o] = W1[i];
    }
    for (int i = tid; i < 2048; i += 128) {        // W2
        int o = i >> 5, c = i & 31;
        sWt2[c * 64 + o] = W2[i];
    }
    for (int i = tid; i < 2048; i += 128) {        // SW
        int o = i >> 5, c = i & 31;
        sWtc[c * 64 + o] = SW[i];
    }
    if (tid < 32) { ss0[tid] = g0[tid] * INVC; sb0[tid] = bb0[tid];
                    ss1[tid] = g1[tid] * INVC; sb1[tid] = bb1[tid]; }
    else if (tid < 96) { int o = tid - 32;
                    ss2[o] = g2[o] * INVC; sb2[o] = bb2[o];
                    ssc[o] = sg[o] * INVC; sbc[o] = sb[o]; }

    const float* __restrict__ fT = g_featT + (size_t)b * NP * CH;

    // ---- stage CF[c][pt] ----
    {
        int pt = tid >> 3;
        int c0 = (tid & 7) * 4;
        float4 v = *(const float4*)(fT + (size_t)(p0 + pt) * CH + c0);
        CF[(c0+0) * TP + pt] = v.x;
        CF[(c0+1) * TP + pt] = v.y;
        CF[(c0+2) * TP + pt] = v.z;
        CF[(c0+3) * TP + pt] = v.w;
    }
    __syncwarp();

    // ---- stage XH: thread handles rows 2*tid, 2*tid+1 (same pt) ----
    {
        int r0s = tid * 2;
        int pt  = r0s >> 4;
        int k0  = r0s & 15;
        const int* ipp = g_idx + (((size_t)b * NP + p0 + pt) << 4);
        int q0 = ipp[k0];
        int q1 = ipp[k0 + 1];
        const float4* qa = (const float4*)(fT + (size_t)q0 * CH);
        const float4* qb = (const float4*)(fT + (size_t)q1 * CH);
        #pragma unroll
        for (int i = 0; i < 8; i++) {
            float4 a0 = qa[i], a1 = qb[i];
            float c0v = CF[(4*i+0) * TP + pt];
            float c1v = CF[(4*i+1) * TP + pt];
            float c2v = CF[(4*i+2) * TP + pt];
            float c3v = CF[(4*i+3) * TP + pt];
            *(float2*)(XA + (4*i+0) * RR_S + r0s) = make_float2(a0.x - c0v, a1.x - c0v);
            *(float2*)(XA + (4*i+1) * RR_S + r0s) = make_float2(a0.y - c1v, a1.y - c1v);
            *(float2*)(XA + (4*i+2) * RR_S + r0s) = make_float2(a0.z - c2v, a1.z - c2v);
            *(float2*)(XA + (4*i+3) * RR_S + r0s) = make_float2(a0.w - c3v, a1.w - c3v);
        }
    }

    __syncthreads();   // only block barrier: weights + staging complete

    // ---- pb0[o][pt] ----
    {
        int pt  = tid >> 3;
        int o0p = (tid & 7) * 4;
        float a0 = 0.f, a1 = 0.f, a2 = 0.f, a3 = 0.f;
        #pragma unroll
        for (int c = 0; c < 32; c++) {
            float4 w = *(const float4*)(sWt0l + c * 32 + o0p);
            float cf = CF[c * TP + pt];
            a0 = fmaf(w.x, cf, a0); a1 = fmaf(w.y, cf, a1);
            a2 = fmaf(w.z, cf, a2); a3 = fmaf(w.w, cf, a3);
        }
        pb0s[(o0p+0) * TP + pt] = fmaf(a0, ss0[o0p+0], sb0[o0p+0]);
        pb0s[(o0p+1) * TP + pt] = fmaf(a1, ss0[o0p+1], sb0[o0p+1]);
        pb0s[(o0p+2) * TP + pt] = fmaf(a2, ss0[o0p+2], sb0[o0p+2]);
        pb0s[(o0p+3) * TP + pt] = fmaf(a3, ss0[o0p+3], sb0[o0p+3]);
    }
    __syncwarp();

    const int w_   = tid >> 5;
    const int lane = tid & 31;
    const int ri   = lane & 3;       // 0..3 row lanes
    const int oq   = lane >> 2;      // 0..7 o-blocks of 4

    gemm_stage<0>(XA, XB, sWt0h, 32, oq * 4, ss0, sb0, pb0s, w_, ri);
    __syncwarp();
    gemm_stage<1>(XB, XA, sWt1,  32, oq * 4, ss1, sb1, pb0s, w_, ri);
    __syncwarp();
    gemm_stage<2>(XA, red, sWt2, 64, oq * 4,      ss2, sb2, pb0s, w_, ri);
    gemm_stage<2>(XA, red, sWt2, 64, 32 + oq * 4, ss2, sb2, pb0s, w_, ri);
    __syncwarp();

    // ---- shortcut + mean + final relu ----
    {
        int pt  = tid >> 3;
        int o0s = (tid & 7) * 8;
        float a[8];
        #pragma unroll
        for (int j = 0; j < 8; j++) a[j] = 0.f;
        #pragma unroll
        for (int c = 0; c < 32; c++) {
            float cf = CF[c * TP + pt];
            float4 w0 = *(const float4*)(sWtc + c * 64 + o0s);
            float4 w1 = *(const float4*)(sWtc + c * 64 + o0s + 4);
            a[0] = fmaf(w0.x, cf, a[0]); a[1] = fmaf(w0.y, cf, a[1]);
            a[2] = fmaf(w0.z, cf, a[2]); a[3] = fmaf(w0.w, cf, a[3]);
            a[4] = fmaf(w1.x, cf, a[4]); a[5] = fmaf(w1.y, cf, a[5]);
            a[6] = fmaf(w1.z, cf, a[6]); a[7] = fmaf(w1.w, cf, a[7]);
        }
        #pragma unroll
        for (int j = 0; j < 8; j++) {
            int o = o0s + j;
            float v = fmaf(a[j], ssc[o], sbc[o]) + red[o * TP + pt] * (1.0f / 16.0f);
            out[((size_t)b * 64 + o) * NP + p0 + pt] = fmaxf(v, 0.f);
        }
    }
}

// ---------------------------------------------------------------------------
extern "C" void kernel_launch(void* const* d_in, const int* in_sizes, int n_in,
                              void* d_out, int out_size)
{
    (void)in_sizes; (void)n_in; (void)out_size;
    const float* features = (const float*)d_in[1];
    const int*   ef       = (const int*)d_in[2];

    static bool attr_set = false;
    if (!attr_set) {
        cudaFuncSetAttribute(main_kernel,
                             cudaFuncAttributeMaxDynamicSharedMemorySize,
                             SMEM_FLOATS * (int)sizeof(float));
        attr_set = true;
    }

    prep_kernel<<<BATCH * 256, 256>>>(ef);
    {
        dim3 tg(EDG / 256, BATCH);
        scatter_kernel<<<tg, 256>>>(ef);
    }
    {
        dim3 tb(32, 8), tg(NP / 32, BATCH);
        transpose_kernel<<<tg, tb>>>(features);
    }
    main_kernel<<<(BATCH * NP) / TP, 128, SMEM_FLOATS * sizeof(float)>>>(
        (const float*)d_in[3],  (const float*)d_in[4],  (const float*)d_in[5],
        (const float*)d_in[6],  (const float*)d_in[7],  (const float*)d_in[8],
        (const float*)d_in[9],  (const float*)d_in[10], (const float*)d_in[11],
        (const float*)d_in[12], (const float*)d_in[13], (const float*)d_in[14],
        (float*)d_out);
}